// round 3
// baseline (speedup 1.0000x reference)
#include <cuda_runtime.h>
#include <cuda_bf16.h>
#include <math.h>

// ---------------- problem constants ----------------
#define NN   20000          // nodes
#define NE   320000         // raw edges
#define NT   (NE + NN)      // edges + self loops = 340000
#define FIN  256
#define H1h  8
#define C1c  128
#define D1   1024           // H1*C1
#define D2   128            // emb size (H2=1, C2=128)

// ---------------- scratch (device globals; referenced ONLY from device code) ----------------
__device__ float g_h1 [(size_t)NN * D1];   // x @ W1           [N, 8, 128]
__device__ float g_out1[(size_t)NN * D1];  // conv1 out / ELU  [N, 1024]
__device__ float g_as1[NN * H1h];
__device__ float g_ad1[NN * H1h];
__device__ float g_m1 [NN * H1h];
__device__ float g_dn1[NN * H1h];
__device__ float g_ex1[(size_t)NT * H1h];
__device__ float g_h2 [(size_t)NN * D2];   // out1 @ W2        [N, 128]
__device__ float g_as2[NN];
__device__ float g_ad2[NN];
__device__ float g_m2 [NN];
__device__ float g_dn2[NN];
__device__ float g_ex2[NT];
__device__ int   g_src[NT];
__device__ int   g_dst[NT];
__device__ int   g_is32;

// ---------------- helpers ----------------
__device__ __forceinline__ void atomicMaxFloat(float* addr, float value) {
    int old = __float_as_int(*addr);
    while (__int_as_float(old) < value) {
        int assumed = old;
        old = atomicCAS((int*)addr, assumed, __float_as_int(value));
        if (old == assumed) break;
    }
}

__device__ __forceinline__ int clampN(long long v) {
    int i = (int)v;
    return i < 0 ? 0 : (i >= NN ? NN - 1 : i);
}

// ---------------- edge dtype detection + decode ----------------
// int64 indices are always in [0, NN). If the buffer is really int32, an
// int64 read fuses two indices -> value >= 2^32 (unless the odd element is 0).
// Checking 8 entries makes misdetection probability ~(1/NN)^8.
__global__ void detect_dtype_kernel(const long long* __restrict__ ei) {
    if (threadIdx.x == 0 && blockIdx.x == 0) {
        int is32 = 0;
        #pragma unroll
        for (int i = 0; i < 8; i++) {
            long long v = ei[i];
            if (v < 0 || v >= NN) { is32 = 1; break; }
        }
        g_is32 = is32;
    }
}

__global__ void decode_edges_kernel(const long long* __restrict__ ei) {
    int e = blockIdx.x * blockDim.x + threadIdx.x;
    if (e >= NT) return;
    int s, d;
    if (e >= NE) {
        s = e - NE; d = s;                       // self loop
    } else if (g_is32) {
        const int* e32 = (const int*)ei;
        s = e32[e]; d = e32[NE + e];
        s = s < 0 ? 0 : (s >= NN ? NN - 1 : s);
        d = d < 0 ? 0 : (d >= NN ? NN - 1 : d);
    } else {
        s = clampN(ei[e]); d = clampN(ei[NE + e]);
    }
    g_src[e] = s; g_dst[e] = d;
}

// ---------------- scratch init ----------------
__global__ void init_scratch_kernel() {
    const float NEG_INF = -3.402823466e+38f;
    size_t i = (size_t)blockIdx.x * blockDim.x + threadIdx.x;
    size_t stride = (size_t)gridDim.x * blockDim.x;
    size_t n = (size_t)NN * D1;
    for (size_t k = i; k < n; k += stride) g_out1[k] = 0.f;
    for (size_t k = i; k < (size_t)NN * H1h; k += stride) { g_m1[k] = NEG_INF; g_dn1[k] = 0.f; }
    for (size_t k = i; k < (size_t)NN; k += stride)        { g_m2[k] = NEG_INF; g_dn2[k] = 0.f; }
}

__global__ void fill_out_kernel(float* __restrict__ p, size_t n) {
    size_t i = (size_t)blockIdx.x * blockDim.x + threadIdx.x;
    size_t stride = (size_t)gridDim.x * blockDim.x;
    for (; i < n; i += stride) p[i] = 0.f;
}

// ---------------- fp32 SIMT GEMM: C[M,N] = A[M,K] @ B[K,N] ----------------
// 64x64 tile, BK=16, 256 threads, 4x4 per thread. Globals selected by `layer`.
__global__ void gemm64_kernel(const float* __restrict__ Ax, const float* __restrict__ B,
                              int layer) {
    const int M = NN;
    const int K = (layer == 1) ? FIN : D1;
    const int N = (layer == 1) ? D1  : D2;
    const float* __restrict__ A = (layer == 1) ? Ax : (const float*)g_out1;
    float* __restrict__ C = (layer == 1) ? g_h1 : g_h2;

    __shared__ float As[16][65];
    __shared__ float Bs[16][64];
    const int t  = threadIdx.x;
    const int ty = t >> 4, tx = t & 15;
    const int rowBase = blockIdx.y * 64;
    const int colBase = blockIdx.x * 64;

    float acc[4][4] = {};

    const int aRow = t >> 2,  aCol = (t & 3)  << 2;   // A tile: 64x16
    const int bRow = t >> 4,  bCol = (t & 15) << 2;   // B tile: 16x64

    for (int k0 = 0; k0 < K; k0 += 16) {
        float4 av = make_float4(0.f, 0.f, 0.f, 0.f);
        if (rowBase + aRow < M)
            av = *reinterpret_cast<const float4*>(A + (size_t)(rowBase + aRow) * K + k0 + aCol);
        As[aCol + 0][aRow] = av.x; As[aCol + 1][aRow] = av.y;
        As[aCol + 2][aRow] = av.z; As[aCol + 3][aRow] = av.w;

        float4 bv = *reinterpret_cast<const float4*>(B + (size_t)(k0 + bRow) * N + colBase + bCol);
        Bs[bRow][bCol + 0] = bv.x; Bs[bRow][bCol + 1] = bv.y;
        Bs[bRow][bCol + 2] = bv.z; Bs[bRow][bCol + 3] = bv.w;

        __syncthreads();
        #pragma unroll
        for (int kk = 0; kk < 16; kk++) {
            float a[4], b[4];
            #pragma unroll
            for (int i = 0; i < 4; i++) a[i] = As[kk][ty * 4 + i];
            #pragma unroll
            for (int j = 0; j < 4; j++) b[j] = Bs[kk][tx * 4 + j];
            #pragma unroll
            for (int i = 0; i < 4; i++)
                #pragma unroll
                for (int j = 0; j < 4; j++)
                    acc[i][j] = fmaf(a[i], b[j], acc[i][j]);
        }
        __syncthreads();
    }

    #pragma unroll
    for (int i = 0; i < 4; i++) {
        int r = rowBase + ty * 4 + i;
        if (r < M) {
            float4 v = make_float4(acc[i][0], acc[i][1], acc[i][2], acc[i][3]);
            *reinterpret_cast<float4*>(C + (size_t)r * N + colBase + tx * 4) = v;
        }
    }
}

// ---------------- per-node attention coefficients ----------------
__global__ void node_alpha_kernel(const float* __restrict__ asrc,
                                  const float* __restrict__ adst,
                                  int layer) {
    const int H = (layer == 1) ? H1h : 1;
    const int C = C1c;
    const int total = NN * H;
    const float* __restrict__ h = (layer == 1) ? g_h1 : g_h2;
    float* __restrict__ as_ = (layer == 1) ? g_as1 : g_as2;
    float* __restrict__ ad_ = (layer == 1) ? g_ad1 : g_ad2;

    int gw = (int)(((size_t)blockIdx.x * blockDim.x + threadIdx.x) >> 5);
    int lane = threadIdx.x & 31;
    if (gw >= total) return;
    int hh = gw % H;
    const float* hp = h + (size_t)gw * C;
    float s = 0.f, d = 0.f;
    for (int c = lane; c < C; c += 32) {
        float v = hp[c];
        s = fmaf(v, asrc[hh * C + c], s);
        d = fmaf(v, adst[hh * C + c], d);
    }
    #pragma unroll
    for (int o = 16; o; o >>= 1) {
        s += __shfl_xor_sync(0xffffffffu, s, o);
        d += __shfl_xor_sync(0xffffffffu, d, o);
    }
    if (lane == 0) { as_[gw] = s; ad_[gw] = d; }
}

// ---------------- edge softmax passes (use decoded g_src/g_dst) ----------------
__global__ void edge_max_kernel(int layer) {
    const int H = (layer == 1) ? H1h : 1;
    const float* __restrict__ as_ = (layer == 1) ? g_as1 : g_as2;
    const float* __restrict__ ad_ = (layer == 1) ? g_ad1 : g_ad2;
    float* __restrict__ m_ = (layer == 1) ? g_m1 : g_m2;

    int idx = blockIdx.x * blockDim.x + threadIdx.x;
    if (idx >= NT * H) return;
    int e = idx / H, hh = idx - e * H;
    int s = g_src[e], d = g_dst[e];
    float v = as_[s * H + hh] + ad_[d * H + hh];
    v = v > 0.f ? v : 0.2f * v;
    atomicMaxFloat(&m_[d * H + hh], v);
}

__global__ void edge_expsum_kernel(int layer) {
    const int H = (layer == 1) ? H1h : 1;
    const float* __restrict__ as_ = (layer == 1) ? g_as1 : g_as2;
    const float* __restrict__ ad_ = (layer == 1) ? g_ad1 : g_ad2;
    const float* __restrict__ m_  = (layer == 1) ? g_m1  : g_m2;
    float* __restrict__ dn_ = (layer == 1) ? g_dn1 : g_dn2;
    float* __restrict__ ex_ = (layer == 1) ? g_ex1 : g_ex2;

    int idx = blockIdx.x * blockDim.x + threadIdx.x;
    if (idx >= NT * H) return;
    int e = idx / H, hh = idx - e * H;
    int s = g_src[e], d = g_dst[e];
    float v = as_[s * H + hh] + ad_[d * H + hh];
    v = v > 0.f ? v : 0.2f * v;
    float ex = __expf(v - m_[d * H + hh]);
    ex_[idx] = ex;
    atomicAdd(&dn_[d * H + hh], ex);
}

// ---------------- layer-1 message scatter: out1[dst] += alpha * h1[src] ----------------
__global__ void scatter1_kernel() {
    int e = blockIdx.x;
    int s = g_src[e], d = g_dst[e];
    __shared__ float coef[H1h];
    int t = threadIdx.x;
    if (t < H1h) coef[t] = g_ex1[(size_t)e * H1h + t] / (g_dn1[d * H1h + t] + 1e-16f);
    __syncthreads();
    const float* hs = g_h1 + (size_t)s * D1;
    float* od = g_out1 + (size_t)d * D1;
    for (int c = t; c < D1; c += 256)
        atomicAdd(&od[c], coef[c >> 7] * hs[c]);
}

// ---------------- bias + ELU ----------------
__global__ void bias_elu_kernel(const float* __restrict__ bias) {
    size_t i = (size_t)blockIdx.x * blockDim.x + threadIdx.x;
    size_t stride = (size_t)gridDim.x * blockDim.x;
    size_t n = (size_t)NN * D1;
    for (; i < n; i += stride) {
        float v = g_out1[i] + bias[i % D1];
        g_out1[i] = v > 0.f ? v : expm1f(v);
    }
}

// ---------------- layer-2 message scatter into output buffer ----------------
__global__ void scatter2_kernel(float* __restrict__ out) {
    int e = blockIdx.x;
    int s = g_src[e], d = g_dst[e];
    float coef = g_ex2[e] / (g_dn2[d] + 1e-16f);
    int t = threadIdx.x;
    atomicAdd(&out[(size_t)d * D2 + t], coef * g_h2[(size_t)s * D2 + t]);
}

// ---------------- bias + log_softmax (in place on out) ----------------
__global__ void logsoftmax_kernel(float* __restrict__ out, const float* __restrict__ bias) {
    int row = blockIdx.x;
    int t = threadIdx.x;                    // 128 threads
    float v = out[(size_t)row * D2 + t] + bias[t];

    __shared__ float red[4];
    float m = v;
    #pragma unroll
    for (int o = 16; o; o >>= 1) m = fmaxf(m, __shfl_xor_sync(0xffffffffu, m, o));
    if ((t & 31) == 0) red[t >> 5] = m;
    __syncthreads();
    float bm = fmaxf(fmaxf(red[0], red[1]), fmaxf(red[2], red[3]));
    __syncthreads();

    float e = __expf(v - bm);
    float s = e;
    #pragma unroll
    for (int o = 16; o; o >>= 1) s += __shfl_xor_sync(0xffffffffu, s, o);
    if ((t & 31) == 0) red[t >> 5] = s;
    __syncthreads();
    float tot = red[0] + red[1] + red[2] + red[3];

    out[(size_t)row * D2 + t] = v - bm - logf(tot);
}

// ---------------- launch ----------------
extern "C" void kernel_launch(void* const* d_in, const int* in_sizes, int n_in,
                              void* d_out, int out_size) {
    const float*     x        = (const float*)d_in[0];
    const long long* ei       = (const long long*)d_in[1];
    const float*     W1       = (const float*)d_in[2];
    const float*     att_src1 = (const float*)d_in[3];
    const float*     att_dst1 = (const float*)d_in[4];
    const float*     bias1    = (const float*)d_in[5];
    const float*     W2       = (const float*)d_in[6];
    const float*     att_src2 = (const float*)d_in[7];
    const float*     att_dst2 = (const float*)d_in[8];
    const float*     bias2    = (const float*)d_in[9];
    float* out = (float*)d_out;

    // ---- decode edges (dtype-robust) + init scratch ----
    detect_dtype_kernel<<<1, 32>>>(ei);
    decode_edges_kernel<<<(NT + 255) / 256, 256>>>(ei);
    init_scratch_kernel<<<4096, 256>>>();
    fill_out_kernel<<<2048, 256>>>(out, (size_t)NN * D2);

    // ---- layer 1 ----
    {
        dim3 g(D1 / 64, (NN + 63) / 64);
        gemm64_kernel<<<g, 256>>>(x, W1, 1);
    }
    node_alpha_kernel<<<(NN * H1h * 32 + 255) / 256, 256>>>(att_src1, att_dst1, 1);
    edge_max_kernel<<<(NT * H1h + 255) / 256, 256>>>(1);
    edge_expsum_kernel<<<(NT * H1h + 255) / 256, 256>>>(1);
    scatter1_kernel<<<NT, 256>>>();
    bias_elu_kernel<<<4096, 256>>>(bias1);

    // ---- layer 2 ----
    {
        dim3 g(D2 / 64, (NN + 63) / 64);
        gemm64_kernel<<<g, 256>>>(x, W2, 2);
    }
    node_alpha_kernel<<<(NN * 32 + 255) / 256, 256>>>(att_src2, att_dst2, 2);
    edge_max_kernel<<<(NT + 255) / 256, 256>>>(2);
    edge_expsum_kernel<<<(NT + 255) / 256, 256>>>(2);
    scatter2_kernel<<<NT, D2>>>(out);

    // ---- log_softmax ----
    logsoftmax_kernel<<<NN, D2>>>(out, bias2);
}

// round 4
// speedup vs baseline: 2.0227x; 2.0227x over previous
#include <cuda_runtime.h>
#include <cuda_bf16.h>
#include <math.h>
#include <float.h>

// ---------------- problem constants ----------------
#define NN   20000          // nodes
#define NE   320000         // raw edges
#define NT   (NE + NN)      // edges + self loops = 340000
#define FIN  256
#define H1h  8
#define C1c  128
#define D1   1024           // H1*C1
#define D2   128            // emb size

// ---------------- scratch (device globals) ----------------
__device__ float g_h1 [(size_t)NN * D1];   // x @ W1           [N, 8, 128]
__device__ float g_out1[(size_t)NN * D1];  // conv1 out (ELU)  [N, 1024]
__device__ float g_h2 [(size_t)NN * D2];   // out1 @ W2        [N, 128]
__device__ float g_as1[NN * H1h];
__device__ float g_ad1[NN * H1h];
__device__ float g_as2[NN];
__device__ float g_ad2[NN];
__device__ int   g_src[NT];
__device__ int   g_dst[NT];
__device__ int   g_cnt[NN];
__device__ int   g_cur[NN];
__device__ int   g_rowptr[NN + 1];
__device__ int   g_ssrc[NT];    // src ids sorted by dst (CSR payload)
__device__ int   g_is32;

// ---------------- edge dtype detection ----------------
// int64 indices are in [0, NN). If the buffer is really int32, an int64 read
// fuses two indices -> out of range with prob ~1 per entry; check 8.
__global__ void detect_dtype_kernel(const long long* __restrict__ ei) {
    if (threadIdx.x == 0 && blockIdx.x == 0) {
        int is32 = 0;
        #pragma unroll
        for (int i = 0; i < 8; i++) {
            long long v = ei[i];
            if (v < 0 || v >= NN) { is32 = 1; break; }
        }
        g_is32 = is32;
    }
}

__global__ void zero_counts_kernel() {
    int i = blockIdx.x * blockDim.x + threadIdx.x;
    if (i < NN) { g_cnt[i] = 0; g_cur[i] = 0; }
}

// decode edges (robust to int32/int64) + dst histogram
__global__ void decode_count_kernel(const long long* __restrict__ ei) {
    int e = blockIdx.x * blockDim.x + threadIdx.x;
    if (e >= NT) return;
    int s, d;
    if (e >= NE) {
        s = e - NE; d = s;                        // self loop
    } else if (g_is32) {
        const int* e32 = (const int*)ei;
        s = e32[e]; d = e32[NE + e];
    } else {
        s = (int)ei[e]; d = (int)ei[NE + e];
    }
    s = s < 0 ? 0 : (s >= NN ? NN - 1 : s);
    d = d < 0 ? 0 : (d >= NN ? NN - 1 : d);
    g_src[e] = s; g_dst[e] = d;
    atomicAdd(&g_cnt[d], 1);
}

// single-block exclusive scan of g_cnt -> g_rowptr (1024 threads x 20 entries)
#define SCAN_T 1024
#define SCAN_C 20
__global__ void scan_kernel() {
    __shared__ int ssum[SCAN_T];
    int t = threadIdx.x;
    int base = t * SCAN_C;
    int loc[SCAN_C];
    int run = 0;
    #pragma unroll
    for (int j = 0; j < SCAN_C; j++) {
        int idx = base + j;
        int v = (idx < NN) ? g_cnt[idx] : 0;
        loc[j] = run; run += v;
    }
    ssum[t] = run;
    __syncthreads();
    for (int off = 1; off < SCAN_T; off <<= 1) {
        int add = (t >= off) ? ssum[t - off] : 0;
        __syncthreads();
        ssum[t] += add;
        __syncthreads();
    }
    int excl = ssum[t] - run;
    #pragma unroll
    for (int j = 0; j < SCAN_C; j++) {
        int idx = base + j;
        if (idx < NN) g_rowptr[idx] = excl + loc[j];
    }
    if (t == SCAN_T - 1) g_rowptr[NN] = ssum[SCAN_T - 1];
}

// bucket-fill CSR payload
__global__ void fill_csr_kernel() {
    int e = blockIdx.x * blockDim.x + threadIdx.x;
    if (e >= NT) return;
    int d = g_dst[e];
    int pos = g_rowptr[d] + atomicAdd(&g_cur[d], 1);
    g_ssrc[pos] = g_src[e];
}

// ---------------- fp32 SIMT GEMM: C[M,N] = A[M,K] @ B[K,N] ----------------
// 64x64 tile, BK=16, 256 threads, 4x4 per thread.
__global__ void gemm64_kernel(const float* __restrict__ Ax, const float* __restrict__ B,
                              int layer) {
    const int M = NN;
    const int K = (layer == 1) ? FIN : D1;
    const int N = (layer == 1) ? D1  : D2;
    const float* __restrict__ A = (layer == 1) ? Ax : (const float*)g_out1;
    float* __restrict__ C = (layer == 1) ? g_h1 : g_h2;

    __shared__ float As[16][65];
    __shared__ float Bs[16][64];
    const int t  = threadIdx.x;
    const int ty = t >> 4, tx = t & 15;
    const int rowBase = blockIdx.y * 64;
    const int colBase = blockIdx.x * 64;

    float acc[4][4] = {};

    const int aRow = t >> 2,  aCol = (t & 3)  << 2;
    const int bRow = t >> 4,  bCol = (t & 15) << 2;

    for (int k0 = 0; k0 < K; k0 += 16) {
        float4 av = make_float4(0.f, 0.f, 0.f, 0.f);
        if (rowBase + aRow < M)
            av = *reinterpret_cast<const float4*>(A + (size_t)(rowBase + aRow) * K + k0 + aCol);
        As[aCol + 0][aRow] = av.x; As[aCol + 1][aRow] = av.y;
        As[aCol + 2][aRow] = av.z; As[aCol + 3][aRow] = av.w;

        float4 bv = *reinterpret_cast<const float4*>(B + (size_t)(k0 + bRow) * N + colBase + bCol);
        Bs[bRow][bCol + 0] = bv.x; Bs[bRow][bCol + 1] = bv.y;
        Bs[bRow][bCol + 2] = bv.z; Bs[bRow][bCol + 3] = bv.w;

        __syncthreads();
        #pragma unroll
        for (int kk = 0; kk < 16; kk++) {
            float a[4], b[4];
            #pragma unroll
            for (int i = 0; i < 4; i++) a[i] = As[kk][ty * 4 + i];
            #pragma unroll
            for (int j = 0; j < 4; j++) b[j] = Bs[kk][tx * 4 + j];
            #pragma unroll
            for (int i = 0; i < 4; i++)
                #pragma unroll
                for (int j = 0; j < 4; j++)
                    acc[i][j] = fmaf(a[i], b[j], acc[i][j]);
        }
        __syncthreads();
    }

    #pragma unroll
    for (int i = 0; i < 4; i++) {
        int r = rowBase + ty * 4 + i;
        if (r < M) {
            float4 v = make_float4(acc[i][0], acc[i][1], acc[i][2], acc[i][3]);
            *reinterpret_cast<float4*>(C + (size_t)r * N + colBase + tx * 4) = v;
        }
    }
}

// ---------------- per-node attention coefficients ----------------
__global__ void node_alpha_kernel(const float* __restrict__ asrc,
                                  const float* __restrict__ adst,
                                  int layer) {
    const int H = (layer == 1) ? H1h : 1;
    const int C = C1c;
    const int total = NN * H;
    const float* __restrict__ h = (layer == 1) ? g_h1 : g_h2;
    float* __restrict__ as_ = (layer == 1) ? g_as1 : g_as2;
    float* __restrict__ ad_ = (layer == 1) ? g_ad1 : g_ad2;

    int gw = (int)(((size_t)blockIdx.x * blockDim.x + threadIdx.x) >> 5);
    int lane = threadIdx.x & 31;
    if (gw >= total) return;
    int hh = gw % H;
    const float* hp = h + (size_t)gw * C;
    float s = 0.f, d = 0.f;
    for (int c = lane; c < C; c += 32) {
        float v = hp[c];
        s = fmaf(v, asrc[hh * C + c], s);
        d = fmaf(v, adst[hh * C + c], d);
    }
    #pragma unroll
    for (int o = 16; o; o >>= 1) {
        s += __shfl_xor_sync(0xffffffffu, s, o);
        d += __shfl_xor_sync(0xffffffffu, d, o);
    }
    if (lane == 0) { as_[gw] = s; ad_[gw] = d; }
}

// ---------------- fused layer-1 gather: softmax + aggregate + bias + ELU ----------------
// one block (256 thr) per dst node; warp h owns head h (channels h*128..h*128+127)
__global__ void gather1_kernel(const float* __restrict__ bias) {
    const int d    = blockIdx.x;
    const int t    = threadIdx.x;
    const int h    = t >> 5;          // warp id == head
    const int lane = t & 31;
    const int row0 = g_rowptr[d];
    const int row1 = g_rowptr[d + 1];

    __shared__ float sm[H1h], sdn[H1h];

    const float ad = g_ad1[d * H1h + h];

    // pass 1a: segmented max (per head, warp-parallel over edges)
    float mx = -FLT_MAX;
    for (int i = row0 + lane; i < row1; i += 32) {
        float v = g_as1[g_ssrc[i] * H1h + h] + ad;
        v = v > 0.f ? v : 0.2f * v;
        mx = fmaxf(mx, v);
    }
    #pragma unroll
    for (int o = 16; o; o >>= 1) mx = fmaxf(mx, __shfl_xor_sync(0xffffffffu, mx, o));

    // pass 1b: segmented exp-sum
    float sum = 0.f;
    for (int i = row0 + lane; i < row1; i += 32) {
        float v = g_as1[g_ssrc[i] * H1h + h] + ad;
        v = v > 0.f ? v : 0.2f * v;
        sum += __expf(v - mx);
    }
    #pragma unroll
    for (int o = 16; o; o >>= 1) sum += __shfl_xor_sync(0xffffffffu, sum, o);

    if (lane == 0) { sm[h] = mx; sdn[h] = sum + 1e-16f; }
    __syncthreads();

    // pass 2: weighted accumulate; thread owns channels [t*4, t*4+4) of head h
    const float m  = sm[h];
    const float dn = sdn[h];
    float4 acc = make_float4(0.f, 0.f, 0.f, 0.f);
    for (int i = row0; i < row1; i++) {
        int s = g_ssrc[i];
        float v = g_as1[s * H1h + h] + ad;      // broadcast load within warp
        v = v > 0.f ? v : 0.2f * v;
        float alpha = __expf(v - m) / dn;
        float4 hv = *reinterpret_cast<const float4*>(&g_h1[(size_t)s * D1 + t * 4]);
        acc.x = fmaf(alpha, hv.x, acc.x);
        acc.y = fmaf(alpha, hv.y, acc.y);
        acc.z = fmaf(alpha, hv.z, acc.z);
        acc.w = fmaf(alpha, hv.w, acc.w);
    }

    // fused bias + ELU, single store
    const float4 bv = *reinterpret_cast<const float4*>(&bias[t * 4]);
    float4 o;
    o.x = acc.x + bv.x; o.y = acc.y + bv.y; o.z = acc.z + bv.z; o.w = acc.w + bv.w;
    o.x = o.x > 0.f ? o.x : expm1f(o.x);
    o.y = o.y > 0.f ? o.y : expm1f(o.y);
    o.z = o.z > 0.f ? o.z : expm1f(o.z);
    o.w = o.w > 0.f ? o.w : expm1f(o.w);
    *reinterpret_cast<float4*>(&g_out1[(size_t)d * D1 + t * 4]) = o;
}

// ---------------- fused layer-2 gather: softmax + aggregate + bias + log_softmax ----------------
// one block (128 thr) per dst node
__global__ void gather2_kernel(float* __restrict__ out, const float* __restrict__ bias) {
    const int d    = blockIdx.x;
    const int t    = threadIdx.x;
    const int lane = t & 31;
    const int row0 = g_rowptr[d];
    const int row1 = g_rowptr[d + 1];

    __shared__ float red[4];
    __shared__ float sm, sdn;

    const float ad = g_ad2[d];

    // pass 1 on warp 0
    if (t < 32) {
        float mx = -FLT_MAX;
        for (int i = row0 + lane; i < row1; i += 32) {
            float v = g_as2[g_ssrc[i]] + ad;
            v = v > 0.f ? v : 0.2f * v;
            mx = fmaxf(mx, v);
        }
        #pragma unroll
        for (int o = 16; o; o >>= 1) mx = fmaxf(mx, __shfl_xor_sync(0xffffffffu, mx, o));
        float sum = 0.f;
        for (int i = row0 + lane; i < row1; i += 32) {
            float v = g_as2[g_ssrc[i]] + ad;
            v = v > 0.f ? v : 0.2f * v;
            sum += __expf(v - mx);
        }
        #pragma unroll
        for (int o = 16; o; o >>= 1) sum += __shfl_xor_sync(0xffffffffu, sum, o);
        if (lane == 0) { sm = mx; sdn = sum + 1e-16f; }
    }
    __syncthreads();

    const float m  = sm;
    const float dn = sdn;

    // pass 2: each thread owns channel t
    float acc = 0.f;
    for (int i = row0; i < row1; i++) {
        int s = g_ssrc[i];
        float v = g_as2[s] + ad;
        v = v > 0.f ? v : 0.2f * v;
        float alpha = __expf(v - m) / dn;
        acc = fmaf(alpha, g_h2[(size_t)s * D2 + t], acc);
    }
    float val = acc + bias[t];

    // fused log_softmax across the 128 channels
    float mv = val;
    #pragma unroll
    for (int o = 16; o; o >>= 1) mv = fmaxf(mv, __shfl_xor_sync(0xffffffffu, mv, o));
    if (lane == 0) red[t >> 5] = mv;
    __syncthreads();
    float bm = fmaxf(fmaxf(red[0], red[1]), fmaxf(red[2], red[3]));
    __syncthreads();

    float e = __expf(val - bm);
    float ss = e;
    #pragma unroll
    for (int o = 16; o; o >>= 1) ss += __shfl_xor_sync(0xffffffffu, ss, o);
    if (lane == 0) red[t >> 5] = ss;
    __syncthreads();
    float tot = red[0] + red[1] + red[2] + red[3];

    out[(size_t)d * D2 + t] = val - bm - logf(tot);
}

// ---------------- launch ----------------
extern "C" void kernel_launch(void* const* d_in, const int* in_sizes, int n_in,
                              void* d_out, int out_size) {
    const float*     x        = (const float*)d_in[0];
    const long long* ei       = (const long long*)d_in[1];
    const float*     W1       = (const float*)d_in[2];
    const float*     att_src1 = (const float*)d_in[3];
    const float*     att_dst1 = (const float*)d_in[4];
    const float*     bias1    = (const float*)d_in[5];
    const float*     W2       = (const float*)d_in[6];
    const float*     att_src2 = (const float*)d_in[7];
    const float*     att_dst2 = (const float*)d_in[8];
    const float*     bias2    = (const float*)d_in[9];
    float* out = (float*)d_out;

    // ---- CSR build (int atomics only, ~30us) ----
    detect_dtype_kernel<<<1, 32>>>(ei);
    zero_counts_kernel<<<(NN + 255) / 256, 256>>>();
    decode_count_kernel<<<(NT + 255) / 256, 256>>>(ei);
    scan_kernel<<<1, SCAN_T>>>();
    fill_csr_kernel<<<(NT + 255) / 256, 256>>>();

    // ---- layer 1 ----
    {
        dim3 g(D1 / 64, (NN + 63) / 64);
        gemm64_kernel<<<g, 256>>>(x, W1, 1);
    }
    node_alpha_kernel<<<(NN * H1h * 32 + 255) / 256, 256>>>(att_src1, att_dst1, 1);
    gather1_kernel<<<NN, 256>>>(bias1);

    // ---- layer 2 ----
    {
        dim3 g(D2 / 64, (NN + 63) / 64);
        gemm64_kernel<<<g, 256>>>(x, W2, 2);
    }
    node_alpha_kernel<<<(NN * 32 + 255) / 256, 256>>>(att_src2, att_dst2, 2);
    gather2_kernel<<<NN, D2>>>(out, bias2);
}